// round 2
// baseline (speedup 1.0000x reference)
#include <cuda_runtime.h>
#include <cstring>

#define NLAYERS 200
#define KSIZE   7
#define L_IN    1388
#define FC_IN   188
#define FC_OUT  91
#define WARPS_PER_CTA 4
#define NT      (32 * WARPS_PER_CTA)
#define C0      44        // initial chunk per lane (44*32 = 1408 >= 1388)
#define STG_N   1024      // per-warp repack stage (float2)

// Packed dual-fp32 FMA (Blackwell f32x2): 2 FMAs per instruction, rt_SMSP=2.
static __device__ __forceinline__ float2 ffma2(float2 a, float2 b, float2 c) {
    unsigned long long ua, ub, uc, ud;
    memcpy(&ua, &a, 8); memcpy(&ub, &b, 8); memcpy(&uc, &c, 8);
    asm("fma.rn.f32x2 %0, %1, %2, %3;" : "=l"(ud) : "l"(ua), "l"(ub), "l"(uc));
    float2 d; memcpy(&d, &ud, 8);
    return d;
}

static __device__ __forceinline__ float2 shfl_down1_f2(float2 v) {
    float2 r;
    r.x = __shfl_down_sync(0xffffffffu, v.x, 1);
    r.y = __shfl_down_sync(0xffffffffu, v.y, 1);
    return r;
}

// One phase of nl conv layers at compile-time chunk count C (blocked layout:
// lane l owns elements [l*C, l*C+C)). In-place ascending update; halo = first
// 6 elements of lane l+1 via SHFL (needed only by the last 6 chunks, which
// are computed last -> shuffle latency hidden). Weights double-buffered.
template<int C>
__device__ __forceinline__ void conv_phase(float2* a, int layer0, int nl,
                                           const float2* __restrict__ ws2,
                                           const float2* __restrict__ bs2)
{
    float2 wbuf[KSIZE]; float2 bbuf;
    #pragma unroll
    for (int k = 0; k < KSIZE; k++) wbuf[k] = ws2[layer0 * KSIZE + k];
    bbuf = bs2[layer0];

    #pragma unroll 1
    for (int i = 0; i < nl; i++) {
        const int L = layer0 + i;
        float2 w[KSIZE];
        #pragma unroll
        for (int k = 0; k < KSIZE; k++) w[k] = wbuf[k];
        const float2 b = bbuf;
        // prefetch next layer's weights (ws2/bs2 are padded by one layer)
        #pragma unroll
        for (int k = 0; k < KSIZE; k++) wbuf[k] = ws2[(L + 1) * KSIZE + k];
        bbuf = bs2[L + 1];

        float2 h[6];
        #pragma unroll
        for (int j = 0; j < 6; j++) h[j] = shfl_down1_f2(a[j]);

        const bool relu = (L != NLAYERS - 1);
        #pragma unroll
        for (int c = 0; c < C; c++) {
            float2 acc = b;
            #pragma unroll
            for (int k = 0; k < KSIZE; k++) {
                float2 v = (c + k < C) ? a[c + k] : h[c + k - C];
                acc = ffma2(w[k], v, acc);
            }
            if (relu) { acc.x = fmaxf(acc.x, 0.0f); acc.y = fmaxf(acc.y, 0.0f); }
            a[c] = acc;   // safe: out[c] only needed by outputs <= c (already done)
        }
    }
}

// Re-block from chunk CO to chunk CN through the per-warp smem stage.
// VIN = current valid input length (compile-time). Garbage beyond VIN zeroed.
template<int CO, int CN, int VIN>
__device__ __forceinline__ void repack(float2* a, float2* stg, int lane)
{
    __syncwarp();
    #pragma unroll
    for (int c = 0; c < CO; c++) {
        int g = lane * CO + c;
        if (g < VIN) stg[g] = a[c];
    }
    __syncwarp();
    #pragma unroll
    for (int c = 0; c < CN; c++) {
        int g = lane * CN + c;
        a[c] = (g < VIN) ? stg[g] : make_float2(0.0f, 0.0f);
    }
    __syncwarp();
}

__global__ __launch_bounds__(NT, 1)
void conv200_kernel(const float* __restrict__ x,
                    const float* __restrict__ conv_w,
                    const float* __restrict__ conv_b,
                    const float* __restrict__ fc_w,
                    const float* __restrict__ fc_b,
                    float* __restrict__ out)
{
    __shared__ float2 stg_all[WARPS_PER_CTA][STG_N];          // 32 KB
    __shared__ float2 ws2[(NLAYERS + 1) * KSIZE];             // 11.2 KB (padded)
    __shared__ float2 bs2[NLAYERS + 1];                       // 1.6 KB

    const int t    = threadIdx.x;
    const int wid  = t >> 5;
    const int lane = t & 31;

    for (int j = t; j < (NLAYERS + 1) * KSIZE; j += NT) {
        float w = (j < NLAYERS * KSIZE) ? conv_w[j] : 0.0f;
        ws2[j] = make_float2(w, w);
    }
    for (int j = t; j < NLAYERS + 1; j += NT) {
        float b = (j < NLAYERS) ? conv_b[j] : 0.0f;
        bs2[j] = make_float2(b, b);
    }
    __syncthreads();   // the ONLY block-wide barrier

    const int pair = blockIdx.x * WARPS_PER_CTA + wid;   // one warp = one row pair
    const int r0   = pair * 2;
    const float* x0 = x + (size_t)r0 * L_IN;
    const float* x1 = x0 + L_IN;
    float2* stg = stg_all[wid];

    // ---- initial load: coalesced window loads -> blocked registers ----
    float2 a[C0];
    for (int j = lane; j < STG_N; j += 32) stg[j] = make_float2(x0[j], x1[j]);
    __syncwarp();
    #pragma unroll
    for (int c = 0; c < C0; c++) {
        int g = lane * C0 + c;
        if (g < STG_N) a[c] = stg[g];
    }
    __syncwarp();
    for (int j = lane; j < L_IN - STG_N; j += 32)
        stg[j] = make_float2(x0[STG_N + j], x1[STG_N + j]);
    __syncwarp();
    #pragma unroll
    for (int c = 0; c < C0; c++) {
        int g = lane * C0 + c;
        if (g >= STG_N) a[c] = (g < L_IN) ? stg[g - STG_N] : make_float2(0.0f, 0.0f);
    }

    // ---- 200 conv layers: phases with shrinking compile-time chunk counts ----
    conv_phase<44>(a,   0, 61, ws2, bs2);
    repack<44, 32, 1022>(a, stg, lane); conv_phase<32>(a,  61, 8, ws2, bs2);
    repack<32, 31,  974>(a, stg, lane); conv_phase<31>(a,  69, 8, ws2, bs2);
    repack<31, 29,  926>(a, stg, lane); conv_phase<29>(a,  77, 8, ws2, bs2);
    repack<29, 28,  878>(a, stg, lane); conv_phase<28>(a,  85, 8, ws2, bs2);
    repack<28, 26,  830>(a, stg, lane); conv_phase<26>(a,  93, 8, ws2, bs2);
    repack<26, 25,  782>(a, stg, lane); conv_phase<25>(a, 101, 8, ws2, bs2);
    repack<25, 23,  734>(a, stg, lane); conv_phase<23>(a, 109, 8, ws2, bs2);
    repack<23, 22,  686>(a, stg, lane); conv_phase<22>(a, 117, 8, ws2, bs2);
    repack<22, 20,  638>(a, stg, lane); conv_phase<20>(a, 125, 8, ws2, bs2);
    repack<20, 19,  590>(a, stg, lane); conv_phase<19>(a, 133, 8, ws2, bs2);
    repack<19, 17,  542>(a, stg, lane); conv_phase<17>(a, 141, 8, ws2, bs2);
    repack<17, 16,  494>(a, stg, lane); conv_phase<16>(a, 149, 8, ws2, bs2);
    repack<16, 14,  446>(a, stg, lane); conv_phase<14>(a, 157, 8, ws2, bs2);
    repack<14, 13,  398>(a, stg, lane); conv_phase<13>(a, 165, 8, ws2, bs2);
    repack<13, 11,  350>(a, stg, lane); conv_phase<11>(a, 173, 8, ws2, bs2);
    repack<11, 10,  302>(a, stg, lane); conv_phase<10>(a, 181, 8, ws2, bs2);
    repack<10,  8,  254>(a, stg, lane); conv_phase< 8>(a, 189, 8, ws2, bs2);
    repack< 8,  7,  206>(a, stg, lane); conv_phase< 7>(a, 197, 3, ws2, bs2);

    // ---- gather final 188 values into smem ----
    __syncwarp();
    #pragma unroll
    for (int c = 0; c < 7; c++) {
        int g = lane * 7 + c;
        if (g < FC_IN) stg[g] = a[c];
    }
    __syncwarp();

    // ---- FC 188->91 + sigmoid: coalesced weight loads + warp reduction,
    //      4 outputs in flight to overlap the SHFL reduction chains ----
    #pragma unroll 1
    for (int ob = 0; ob < 92; ob += 4) {
        float2 acc[4];
        #pragma unroll
        for (int u = 0; u < 4; u++) acc[u] = make_float2(0.0f, 0.0f);
        #pragma unroll
        for (int u = 0; u < 4; u++) {
            int o  = ob + u;
            int oc = (o < FC_OUT) ? o : (FC_OUT - 1);
            const float* wrow = fc_w + oc * FC_IN;
            #pragma unroll
            for (int jj = 0; jj < 6; jj++) {
                int j = lane + 32 * jj;
                if (j < FC_IN) {
                    float wv = __ldg(&wrow[j]);
                    acc[u] = ffma2(make_float2(wv, wv), stg[j], acc[u]);
                }
            }
        }
        #pragma unroll
        for (int s = 16; s > 0; s >>= 1) {
            #pragma unroll
            for (int u = 0; u < 4; u++) {
                acc[u].x += __shfl_xor_sync(0xffffffffu, acc[u].x, s);
                acc[u].y += __shfl_xor_sync(0xffffffffu, acc[u].y, s);
            }
        }
        if (lane == 0) {
            #pragma unroll
            for (int u = 0; u < 4; u++) {
                int o = ob + u;
                if (o < FC_OUT) {
                    float vb = fc_b[o];
                    out[(size_t)r0 * FC_OUT + o]       = 1.0f / (1.0f + __expf(-(acc[u].x + vb)));
                    out[(size_t)(r0 + 1) * FC_OUT + o] = 1.0f / (1.0f + __expf(-(acc[u].y + vb)));
                }
            }
        }
    }
}

extern "C" void kernel_launch(void* const* d_in, const int* in_sizes, int n_in,
                              void* d_out, int out_size)
{
    const float* x      = (const float*)d_in[0];   // [1024, 1388]
    const float* conv_w = (const float*)d_in[1];   // [200, 7]
    const float* conv_b = (const float*)d_in[2];   // [200]
    const float* fc_w   = (const float*)d_in[3];   // [91, 188]
    const float* fc_b   = (const float*)d_in[4];   // [91]
    float* out          = (float*)d_out;           // [1024, 91]

    const int B     = in_sizes[0] / L_IN;          // 1024
    const int pairs = B / 2;                       // 512
    conv200_kernel<<<pairs / WARPS_PER_CTA, NT>>>(x, conv_w, conv_b, fc_w, fc_b, out);
}

// round 3
// speedup vs baseline: 1.1029x; 1.1029x over previous
#include <cuda_runtime.h>
#include <cstring>

#define NLAYERS 200
#define KSIZE   7
#define L_IN    1388
#define NPAIR   694       // L_IN/2 pairs per row
#define FC_IN   188
#define FC_OUT  91
#define WARPS_PER_CTA 4
#define NT      (32 * WARPS_PER_CTA)
#define C0      22        // initial pairs per lane (22*32 = 704 >= 694)
#define STG_N   704       // per-warp stage (float2 pairs)

// Packed dual-fp32 FMA (Blackwell f32x2): 2 FMAs/instr, full fp32 rate.
static __device__ __forceinline__ float2 ffma2(float2 a, float2 b, float2 c) {
    unsigned long long ua, ub, uc, ud;
    memcpy(&ua, &a, 8); memcpy(&ub, &b, 8); memcpy(&uc, &c, 8);
    asm("fma.rn.f32x2 %0, %1, %2, %3;" : "=l"(ud) : "l"(ua), "l"(ub), "l"(uc));
    float2 d; memcpy(&d, &ud, 8);
    return d;
}

static __device__ __forceinline__ float2 shfl_down1_f2(float2 v) {
    float2 r;
    r.x = __shfl_down_sync(0xffffffffu, v.x, 1);
    r.y = __shfl_down_sync(0xffffffffu, v.y, 1);
    return r;
}

// nl conv layers at compile-time pair-chunk C. Lane l owns pairs [l*C, l*C+C)
// of ONE row, each pair = (h[2g], h[2g+1]). Halo = first 3 pairs of lane l+1
// via SHFL. Misaligned pairs sv[idx] = (v[idx].y, v[idx+1].x) precomputed per
// layer from OLD values, so the ascending in-place update is safe.
template<int C>
__device__ __forceinline__ void conv_phase(float2* p, int layer0, int nl,
                                           const float2* __restrict__ ws2,
                                           const float2* __restrict__ bs2)
{
    float2 wbuf[KSIZE]; float2 bbuf;
    #pragma unroll
    for (int k = 0; k < KSIZE; k++) wbuf[k] = ws2[layer0 * KSIZE + k];
    bbuf = bs2[layer0];

    #pragma unroll 1
    for (int i = 0; i < nl; i++) {
        const int L = layer0 + i;
        float2 w[KSIZE];
        #pragma unroll
        for (int k = 0; k < KSIZE; k++) w[k] = wbuf[k];
        const float2 b = bbuf;
        #pragma unroll
        for (int k = 0; k < KSIZE; k++) wbuf[k] = ws2[(L + 1) * KSIZE + k];
        bbuf = bs2[L + 1];

        float2 h[3];
        #pragma unroll
        for (int j = 0; j < 3; j++) h[j] = shfl_down1_f2(p[j]);

        // v(idx) = idx<C ? p[idx] : h[idx-C], idx in [0, C+3)
        // misaligned pairs, from OLD values (copies -> in-place loop safe)
        float2 sv[C + 2];
        #pragma unroll
        for (int idx = 0; idx < C + 2; idx++) {
            float lo = (idx     < C) ? p[idx].y     : h[idx - C].y;
            float hi = (idx + 1 < C) ? p[idx + 1].x : h[idx + 1 - C].x;
            sv[idx] = make_float2(lo, hi);
        }

        const bool relu = (L != NLAYERS - 1);
        #pragma unroll
        for (int j = 0; j < C; j++) {
            float2 acc = b;
            acc = ffma2(w[0], p[j], acc);
            acc = ffma2(w[2], (j + 1 < C) ? p[j + 1] : h[j + 1 - C], acc);
            acc = ffma2(w[4], (j + 2 < C) ? p[j + 2] : h[j + 2 - C], acc);
            acc = ffma2(w[6], (j + 3 < C) ? p[j + 3] : h[j + 3 - C], acc);
            acc = ffma2(w[1], sv[j],     acc);
            acc = ffma2(w[3], sv[j + 1], acc);
            acc = ffma2(w[5], sv[j + 2], acc);
            if (relu) { acc.x = fmaxf(acc.x, 0.0f); acc.y = fmaxf(acc.y, 0.0f); }
            p[j] = acc;
        }
    }
}

// Re-block from pair-chunk CO to CN through the per-warp smem stage.
// VIN = valid input PAIRS at the next phase's first layer; zero beyond.
template<int CO, int CN, int VIN>
__device__ __forceinline__ void repack(float2* p, float2* stg, int lane)
{
    __syncwarp();
    #pragma unroll
    for (int c = 0; c < CO; c++) {
        int g = lane * CO + c;
        if (g < VIN) stg[g] = p[c];
    }
    __syncwarp();
    #pragma unroll
    for (int c = 0; c < CN; c++) {
        int g = lane * CN + c;
        p[c] = (g < VIN) ? stg[g] : make_float2(0.0f, 0.0f);
    }
    __syncwarp();
}

__global__ __launch_bounds__(NT, 2)
void conv200_kernel(const float* __restrict__ x,
                    const float* __restrict__ conv_w,
                    const float* __restrict__ conv_b,
                    const float* __restrict__ fc_w,
                    const float* __restrict__ fc_b,
                    float* __restrict__ out)
{
    __shared__ float2 stg_all[WARPS_PER_CTA][STG_N];          // 22.5 KB
    __shared__ float2 ws2[(NLAYERS + 1) * KSIZE];             // 11.3 KB
    __shared__ float2 bs2[NLAYERS + 1];                       // 1.6 KB

    const int t    = threadIdx.x;
    const int wid  = t >> 5;
    const int lane = t & 31;

    for (int j = t; j < (NLAYERS + 1) * KSIZE; j += NT) {
        float w = (j < NLAYERS * KSIZE) ? conv_w[j] : 0.0f;
        ws2[j] = make_float2(w, w);
    }
    for (int j = t; j < NLAYERS + 1; j += NT) {
        float b = (j < NLAYERS) ? conv_b[j] : 0.0f;
        bs2[j] = make_float2(b, b);
    }
    __syncthreads();   // only block-wide barrier

    const int row = blockIdx.x * WARPS_PER_CTA + wid;   // one warp = one row
    const float2* xr = reinterpret_cast<const float2*>(x + (size_t)row * L_IN);
    float2* stg = stg_all[wid];

    // coalesced load -> blocked registers (pairs are natural float2 loads)
    for (int j = lane; j < STG_N; j += 32)
        stg[j] = (j < NPAIR) ? xr[j] : make_float2(0.0f, 0.0f);
    __syncwarp();
    float2 p[C0];
    #pragma unroll
    for (int c = 0; c < C0; c++) p[c] = stg[lane * C0 + c];

    // ---- 200 conv layers, shrinking compile-time pair-chunks ----
    conv_phase<22>(p,   0,  8, ws2, bs2);
    repack<22, 21, 670>(p, stg, lane); conv_phase<21>(p,   8, 10, ws2, bs2);
    repack<21, 20, 640>(p, stg, lane); conv_phase<20>(p,  18, 11, ws2, bs2);
    repack<20, 19, 607>(p, stg, lane); conv_phase<19>(p,  29, 11, ws2, bs2);
    repack<19, 18, 574>(p, stg, lane); conv_phase<18>(p,  40, 10, ws2, bs2);
    repack<18, 17, 544>(p, stg, lane); conv_phase<17>(p,  50, 11, ws2, bs2);
    repack<17, 16, 511>(p, stg, lane); conv_phase<16>(p,  61, 11, ws2, bs2);
    repack<16, 15, 478>(p, stg, lane); conv_phase<15>(p,  72, 10, ws2, bs2);
    repack<15, 14, 448>(p, stg, lane); conv_phase<14>(p,  82, 11, ws2, bs2);
    repack<14, 13, 415>(p, stg, lane); conv_phase<13>(p,  93, 11, ws2, bs2);
    repack<13, 12, 382>(p, stg, lane); conv_phase<12>(p, 104, 10, ws2, bs2);
    repack<12, 11, 352>(p, stg, lane); conv_phase<11>(p, 114, 11, ws2, bs2);
    repack<11, 10, 319>(p, stg, lane); conv_phase<10>(p, 125, 11, ws2, bs2);
    repack<10,  9, 286>(p, stg, lane); conv_phase< 9>(p, 136, 10, ws2, bs2);
    repack< 9,  8, 256>(p, stg, lane); conv_phase< 8>(p, 146, 11, ws2, bs2);
    repack< 8,  7, 223>(p, stg, lane); conv_phase< 7>(p, 157, 11, ws2, bs2);
    repack< 7,  6, 190>(p, stg, lane); conv_phase< 6>(p, 168, 10, ws2, bs2);
    repack< 6,  5, 160>(p, stg, lane); conv_phase< 5>(p, 178, 11, ws2, bs2);
    repack< 5,  4, 127>(p, stg, lane); conv_phase< 4>(p, 189, 11, ws2, bs2);

    // ---- gather final 94 valid pairs (188 elements) ----
    __syncwarp();
    #pragma unroll
    for (int c = 0; c < 4; c++) {
        int g = lane * 4 + c;
        if (g < FC_IN / 2) stg[g] = p[c];
    }
    __syncwarp();

    // ---- FC 188->91 + sigmoid: lane handles outputs {lane, lane+32, lane+64},
    //      one pass over the 94 input pairs, 3 dot products in flight ----
    {
        const float2* fw2 = reinterpret_cast<const float2*>(fc_w);
        float2 acc[3];
        #pragma unroll
        for (int u = 0; u < 3; u++) acc[u] = make_float2(0.0f, 0.0f);
        int o0 = lane, o1 = lane + 32, o2 = lane + 64;
        int c2 = (o2 < FC_OUT) ? o2 : (FC_OUT - 1);
        const float2* r0w = fw2 + (size_t)o0 * (FC_IN / 2);
        const float2* r1w = fw2 + (size_t)o1 * (FC_IN / 2);
        const float2* r2w = fw2 + (size_t)c2 * (FC_IN / 2);
        #pragma unroll 2
        for (int j = 0; j < FC_IN / 2; j++) {
            float2 hv = stg[j];
            acc[0] = ffma2(__ldg(&r0w[j]), hv, acc[0]);
            acc[1] = ffma2(__ldg(&r1w[j]), hv, acc[1]);
            acc[2] = ffma2(__ldg(&r2w[j]), hv, acc[2]);
        }
        float* orow = out + (size_t)row * FC_OUT;
        float s0 = acc[0].x + acc[0].y + fc_b[o0];
        float s1 = acc[1].x + acc[1].y + fc_b[o1];
        orow[o0] = 1.0f / (1.0f + __expf(-s0));
        orow[o1] = 1.0f / (1.0f + __expf(-s1));
        if (o2 < FC_OUT) {
            float s2 = acc[2].x + acc[2].y + fc_b[o2];
            orow[o2] = 1.0f / (1.0f + __expf(-s2));
        }
    }
}

extern "C" void kernel_launch(void* const* d_in, const int* in_sizes, int n_in,
                              void* d_out, int out_size)
{
    const float* x      = (const float*)d_in[0];   // [1024, 1388]
    const float* conv_w = (const float*)d_in[1];   // [200, 7]
    const float* conv_b = (const float*)d_in[2];   // [200]
    const float* fc_w   = (const float*)d_in[3];   // [91, 188]
    const float* fc_b   = (const float*)d_in[4];   // [91]
    float* out          = (float*)d_out;           // [1024, 91]

    const int B = in_sizes[0] / L_IN;              // 1024 rows
    conv200_kernel<<<B / WARPS_PER_CTA, NT>>>(x, conv_w, conv_b, fc_w, fc_b, out);
}

// round 4
// speedup vs baseline: 1.1536x; 1.0459x over previous
#include <cuda_runtime.h>
#include <cstring>

#define NLAYERS 200
#define KSIZE   7
#define L_IN    1388
#define NPAIR   694       // L_IN/2 pairs per row
#define FC_IN   188
#define FC_OUT  91
#define WARPS_PER_CTA 8
#define NT      (32 * WARPS_PER_CTA)
#define C0      22        // initial pairs per lane (22*32 = 704 >= 694)
#define STG_N   704       // per-warp stage (float2 pairs)

// Packed dual-fp32 FMA (Blackwell f32x2): 2 FMAs/instr, full fp32 rate.
static __device__ __forceinline__ float2 ffma2(float2 a, float2 b, float2 c) {
    unsigned long long ua, ub, uc, ud;
    memcpy(&ua, &a, 8); memcpy(&ub, &b, 8); memcpy(&uc, &c, 8);
    asm("fma.rn.f32x2 %0, %1, %2, %3;" : "=l"(ud) : "l"(ua), "l"(ub), "l"(uc));
    float2 d; memcpy(&d, &ud, 8);
    return d;
}

static __device__ __forceinline__ float2 shfl_down1_f2(float2 v) {
    float2 r;
    r.x = __shfl_down_sync(0xffffffffu, v.x, 1);
    r.y = __shfl_down_sync(0xffffffffu, v.y, 1);
    return r;
}

// nl conv layers at compile-time pair-chunk C. Lane l owns pairs [l*C, l*C+C)
// of ONE row, pair = (h[2g], h[2g+1]). Halo = first 3 pairs of lane l+1 via
// SHFL. Misaligned pairs handled by a ROLLING 3-register window (s0,s1,s2):
// each is built once (2 MOVs) and lives 3 iterations -> low reg pressure.
// Weights prefetched one layer ahead from global (L1-resident, 5.7KB hot).
template<int C>
__device__ __forceinline__ void conv_phase(float2* p, int layer0, int nl,
                                           const float* __restrict__ cw,
                                           const float* __restrict__ cb)
{
    float wb[KSIZE], bb;
    #pragma unroll
    for (int k = 0; k < KSIZE; k++) wb[k] = __ldg(&cw[layer0 * KSIZE + k]);
    bb = __ldg(&cb[layer0]);

    #pragma unroll 1
    for (int i = 0; i < nl; i++) {
        const int L = layer0 + i;
        float2 w[KSIZE];
        #pragma unroll
        for (int k = 0; k < KSIZE; k++) w[k] = make_float2(wb[k], wb[k]);
        const float2 b = make_float2(bb, bb);

        const int Ln = (L + 1 < NLAYERS) ? L + 1 : L;   // prefetch next layer
        #pragma unroll
        for (int k = 0; k < KSIZE; k++) wb[k] = __ldg(&cw[Ln * KSIZE + k]);
        bb = __ldg(&cb[Ln]);

        float2 h[3];
        #pragma unroll
        for (int j = 0; j < 3; j++) h[j] = shfl_down1_f2(p[j]);

        // rolling misaligned pairs: sv(i) = (val(i).y, val(i+1).x)
        float2 s0 = make_float2(p[0].y, p[1].x);
        float2 s1 = make_float2(p[1].y, p[2].x);
        float2 s2 = make_float2(p[2].y, p[3].x);   // C >= 4 always

        const bool relu = (L != NLAYERS - 1);
        #pragma unroll
        for (int j = 0; j < C; j++) {
            float2 v1 = (j + 1 < C) ? p[j + 1] : h[j + 1 - C];
            float2 v2 = (j + 2 < C) ? p[j + 2] : h[j + 2 - C];
            float2 v3 = (j + 3 < C) ? p[j + 3] : h[j + 3 - C];
            float2 acc = b;
            acc = ffma2(w[0], p[j], acc);
            acc = ffma2(w[1], s0,   acc);
            acc = ffma2(w[2], v1,   acc);
            acc = ffma2(w[3], s1,   acc);
            acc = ffma2(w[4], v2,   acc);
            acc = ffma2(w[5], s2,   acc);
            acc = ffma2(w[6], v3,   acc);
            float2 snext = s2;
            if (j < C - 1) {
                float2 v4 = (j + 4 < C) ? p[j + 4] : h[j + 4 - C];
                snext = make_float2(v3.y, v4.x);
            }
            if (relu) { acc.x = fmaxf(acc.x, 0.0f); acc.y = fmaxf(acc.y, 0.0f); }
            p[j] = acc;
            s0 = s1; s1 = s2; s2 = snext;
        }
    }
}

// Re-block from pair-chunk CO to CN through the per-warp smem stage.
// VIN = valid input PAIRS at the next phase's first layer; zero beyond.
template<int CO, int CN, int VIN>
__device__ __forceinline__ void repack(float2* p, float2* stg, int lane)
{
    __syncwarp();
    #pragma unroll
    for (int c = 0; c < CO; c++) {
        int g = lane * CO + c;
        if (g < VIN) stg[g] = p[c];
    }
    __syncwarp();
    #pragma unroll
    for (int c = 0; c < CN; c++) {
        int g = lane * CN + c;
        p[c] = (g < VIN) ? stg[g] : make_float2(0.0f, 0.0f);
    }
    __syncwarp();
}

__global__ __launch_bounds__(NT, 1)
void conv200_kernel(const float* __restrict__ x,
                    const float* __restrict__ conv_w,
                    const float* __restrict__ conv_b,
                    const float* __restrict__ fc_w,
                    const float* __restrict__ fc_b,
                    float* __restrict__ out)
{
    __shared__ float2 stg_all[WARPS_PER_CTA][STG_N];   // 44 KB, per-warp stages

    const int t    = threadIdx.x;
    const int wid  = t >> 5;
    const int lane = t & 31;

    const int row = blockIdx.x * WARPS_PER_CTA + wid;   // one warp = one row
    const float2* xr = reinterpret_cast<const float2*>(x + (size_t)row * L_IN);
    float2* stg = stg_all[wid];

    // coalesced load -> blocked registers (pairs are natural float2 loads)
    for (int j = lane; j < STG_N; j += 32)
        stg[j] = (j < NPAIR) ? __ldg(&xr[j]) : make_float2(0.0f, 0.0f);
    __syncwarp();
    float2 p[C0];
    #pragma unroll
    for (int c = 0; c < C0; c++) p[c] = stg[lane * C0 + c];

    // ---- 200 conv layers, shrinking compile-time pair-chunks ----
    conv_phase<22>(p,   0,  8, conv_w, conv_b);
    repack<22, 21, 670>(p, stg, lane); conv_phase<21>(p,   8, 10, conv_w, conv_b);
    repack<21, 20, 640>(p, stg, lane); conv_phase<20>(p,  18, 11, conv_w, conv_b);
    repack<20, 19, 607>(p, stg, lane); conv_phase<19>(p,  29, 11, conv_w, conv_b);
    repack<19, 18, 574>(p, stg, lane); conv_phase<18>(p,  40, 10, conv_w, conv_b);
    repack<18, 17, 544>(p, stg, lane); conv_phase<17>(p,  50, 11, conv_w, conv_b);
    repack<17, 16, 511>(p, stg, lane); conv_phase<16>(p,  61, 11, conv_w, conv_b);
    repack<16, 15, 478>(p, stg, lane); conv_phase<15>(p,  72, 10, conv_w, conv_b);
    repack<15, 14, 448>(p, stg, lane); conv_phase<14>(p,  82, 11, conv_w, conv_b);
    repack<14, 13, 415>(p, stg, lane); conv_phase<13>(p,  93, 11, conv_w, conv_b);
    repack<13, 12, 382>(p, stg, lane); conv_phase<12>(p, 104, 10, conv_w, conv_b);
    repack<12, 11, 352>(p, stg, lane); conv_phase<11>(p, 114, 11, conv_w, conv_b);
    repack<11, 10, 319>(p, stg, lane); conv_phase<10>(p, 125, 11, conv_w, conv_b);
    repack<10,  9, 286>(p, stg, lane); conv_phase< 9>(p, 136, 10, conv_w, conv_b);
    repack< 9,  8, 256>(p, stg, lane); conv_phase< 8>(p, 146, 11, conv_w, conv_b);
    repack< 8,  7, 223>(p, stg, lane); conv_phase< 7>(p, 157, 11, conv_w, conv_b);
    repack< 7,  6, 190>(p, stg, lane); conv_phase< 6>(p, 168, 10, conv_w, conv_b);
    repack< 6,  5, 160>(p, stg, lane); conv_phase< 5>(p, 178, 11, conv_w, conv_b);
    repack< 5,  4, 127>(p, stg, lane); conv_phase< 4>(p, 189, 11, conv_w, conv_b);

    // ---- gather final 94 valid pairs (188 elements) ----
    __syncwarp();
    #pragma unroll
    for (int c = 0; c < 4; c++) {
        int g = lane * 4 + c;
        if (g < FC_IN / 2) stg[g] = p[c];
    }
    __syncwarp();

    // ---- FC 188->91 + sigmoid: lane handles outputs {lane, lane+32, lane+64},
    //      one pass over the 94 input pairs, 3 dot products in flight ----
    {
        const float2* fw2 = reinterpret_cast<const float2*>(fc_w);
        float2 acc[3];
        #pragma unroll
        for (int u = 0; u < 3; u++) acc[u] = make_float2(0.0f, 0.0f);
        int o0 = lane, o1 = lane + 32, o2 = lane + 64;
        int c2 = (o2 < FC_OUT) ? o2 : (FC_OUT - 1);
        const float2* r0w = fw2 + (size_t)o0 * (FC_IN / 2);
        const float2* r1w = fw2 + (size_t)o1 * (FC_IN / 2);
        const float2* r2w = fw2 + (size_t)c2 * (FC_IN / 2);
        #pragma unroll 2
        for (int j = 0; j < FC_IN / 2; j++) {
            float2 hv = stg[j];
            acc[0] = ffma2(__ldg(&r0w[j]), hv, acc[0]);
            acc[1] = ffma2(__ldg(&r1w[j]), hv, acc[1]);
            acc[2] = ffma2(__ldg(&r2w[j]), hv, acc[2]);
        }
        float* orow = out + (size_t)row * FC_OUT;
        float s0 = acc[0].x + acc[0].y + __ldg(&fc_b[o0]);
        float s1 = acc[1].x + acc[1].y + __ldg(&fc_b[o1]);
        orow[o0] = 1.0f / (1.0f + __expf(-s0));
        orow[o1] = 1.0f / (1.0f + __expf(-s1));
        if (o2 < FC_OUT) {
            float s2 = acc[2].x + acc[2].y + __ldg(&fc_b[o2]);
            orow[o2] = 1.0f / (1.0f + __expf(-s2));
        }
    }
}

extern "C" void kernel_launch(void* const* d_in, const int* in_sizes, int n_in,
                              void* d_out, int out_size)
{
    const float* x      = (const float*)d_in[0];   // [1024, 1388]
    const float* conv_w = (const float*)d_in[1];   // [200, 7]
    const float* conv_b = (const float*)d_in[2];   // [200]
    const float* fc_w   = (const float*)d_in[3];   // [91, 188]
    const float* fc_b   = (const float*)d_in[4];   // [91]
    float* out          = (float*)d_out;           // [1024, 91]

    const int B = in_sizes[0] / L_IN;              // 1024 rows
    conv200_kernel<<<B / WARPS_PER_CTA, NT>>>(x, conv_w, conv_b, fc_w, fc_b, out);
}